// round 13
// baseline (speedup 1.0000x reference)
#include <cuda_runtime.h>
#include <cuda_fp16.h>

// HyperDiffusion: N=100000, E=50000, C=128, NNZ=1600000.
// Bucket CSR + warp-per-row fp16 gathers. Issue-bound per ncu →
// 16-lane dual-stream LDG.128 gathers, depth-2 HADD2 tree (5 instr/member),
// softmax weights hoisted to a precomputed table.

#define NN        100000
#define NE        50000
#define NC        128
#define NC2       (NC / 2)        // 64 half2 per row
#define NCU4      (NC / 8)        // 16 uint4 per row
#define NNZV      1600000
#define NODE_CAP  96
#define EDGE_CAP  128
#define NODE_ARENA ((long)NN * NODE_CAP)              // 9.6M
#define ARENA_TOT  (NODE_ARENA + (long)NE * EDGE_CAP) // 16.0M ints

__device__ int    g_cur[NN + NE];                // fill cursors
__device__ int    g_payload[ARENA_TOT];          // PRE-SCALED uint4-row offsets (id*16)
__device__ float  g_s0[NC];                      // softmax(lazy_w)[0] per channel
__device__ __half g_xnorm[(size_t)NN * NC];      // X * inv_deg_v, fp16
__device__ __half g_enorm[(size_t)NE * NC];      // edge_feat * inv_deg_e, fp16

// ---------------------------------------------------------------------------
__global__ void init_cur(const float* __restrict__ lw) {
    int i = blockIdx.x * blockDim.x + threadIdx.x;
    if (i < NN) g_cur[i] = i * NODE_CAP;
    else if (i < NN + NE) g_cur[i] = (int)(NODE_ARENA + (long)(i - NN) * EDGE_CAP);
    if (i < NC) g_s0[i] = 1.0f / (1.0f + expf(lw[NC + i] - lw[i]));
}

// ---------------------------------------------------------------------------
__global__ void fill_k(const int* __restrict__ ni, const int* __restrict__ ei) {
    int i = blockIdx.x * blockDim.x + threadIdx.x;
    if (i >= NNZV) return;
    int n = ni[i];
    int e = ei[i];
    int p1 = atomicAdd(&g_cur[n], 1);
    int p2 = atomicAdd(&g_cur[NN + e], 1);
    if (p1 < n * NODE_CAP + NODE_CAP) g_payload[p1] = e * NCU4;
    if ((long)p2 < NODE_ARENA + (long)e * EDGE_CAP + EDGE_CAP) g_payload[p2] = n * NCU4;
}

// ---------------------------------------------------------------------------
__global__ void xnorm_k(const float* __restrict__ X) {
    long i = (long)blockIdx.x * blockDim.x + threadIdx.x;   // over NN*NC2
    if (i >= (long)NN * NC2) return;
    int n = (int)(i >> 6);                                  // NC2 = 64
    float2 x = reinterpret_cast<const float2*>(X)[i];
    int d = __ldg(&g_cur[n]) - n * NODE_CAP;
    float inv = (d > 0) ? (1.0f / (float)d) : 0.0f;
    reinterpret_cast<__half2*>(g_xnorm)[i] = __floats2half2_rn(x.x * inv, x.y * inv);
}

// ---------------------------------------------------------------------------
// fp16 helpers
// ---------------------------------------------------------------------------
__device__ __forceinline__ uint4 hadd4(uint4 x, uint4 y) {
    uint4 r;
    __half2*       rr = reinterpret_cast<__half2*>(&r);
    const __half2* xx = reinterpret_cast<const __half2*>(&x);
    const __half2* yy = reinterpret_cast<const __half2*>(&y);
    rr[0] = __hadd2(xx[0], yy[0]);
    rr[1] = __hadd2(xx[1], yy[1]);
    rr[2] = __hadd2(xx[2], yy[2]);
    rr[3] = __hadd2(xx[3], yy[3]);
    return r;
}

__device__ __forceinline__ void cvt_acc(uint4 r, float* a) {
    const __half2* h = reinterpret_cast<const __half2*>(&r);
    float2 f;
    f = __half22float2(h[0]); a[0] += f.x; a[1] += f.y;
    f = __half22float2(h[1]); a[2] += f.x; a[3] += f.y;
    f = __half22float2(h[2]); a[4] += f.x; a[5] += f.y;
    f = __half22float2(h[3]); a[6] += f.x; a[7] += f.y;
}

// ---------------------------------------------------------------------------
// 16-lane dual-stream gather: lanes [0,16) = stream A (even members),
// lanes [16,32) = stream B (odd members). Lane owns 8 channels (1 uint4).
// Depth-2 fp16 tree: 4 loads/stream combined before fp32 conversion.
// ---------------------------------------------------------------------------
__device__ __forceinline__ void gather16(const uint4* __restrict__ src,
                                         long beg, int cnt,
                                         int sub, int sl, int lane, float* a) {
    for (int base = 0; base < cnt; base += 32) {
        int k = base + lane;
        int m = (k < cnt) ? g_payload[beg + k] : 0;
        int lim = min(32, cnt - base);
        int steps = lim >> 1;                    // dual-stream member pairs
        int s = 0;
        for (; s + 4 <= steps; s += 4) {
            int m0 = __shfl_sync(0xffffffffu, m, 2 * s + sub);
            int m1 = __shfl_sync(0xffffffffu, m, 2 * s + 2 + sub);
            int m2 = __shfl_sync(0xffffffffu, m, 2 * s + 4 + sub);
            int m3 = __shfl_sync(0xffffffffu, m, 2 * s + 6 + sub);
            uint4 r0 = __ldg(&src[(unsigned)(m0 + sl)]);
            uint4 r1 = __ldg(&src[(unsigned)(m1 + sl)]);
            uint4 r2 = __ldg(&src[(unsigned)(m2 + sl)]);
            uint4 r3 = __ldg(&src[(unsigned)(m3 + sl)]);
            cvt_acc(hadd4(hadd4(r0, r1), hadd4(r2, r3)), a);
        }
        for (; s < steps; s++) {
            int mi = __shfl_sync(0xffffffffu, m, 2 * s + sub);
            cvt_acc(__ldg(&src[(unsigned)(mi + sl)]), a);
        }
        if (lim & 1) {                           // last unpaired member: stream A only
            int mi = __shfl_sync(0xffffffffu, m, lim - 1);
            if (sub == 0) cvt_acc(__ldg(&src[(unsigned)(mi + sl)]), a);
        }
    }
    #pragma unroll
    for (int q = 0; q < 8; q++)                  // merge the two streams
        a[q] += __shfl_xor_sync(0xffffffffu, a[q], 16);
}

// ---------------------------------------------------------------------------
// v2e: one WARP per edge.
// ---------------------------------------------------------------------------
__global__ void __launch_bounds__(128) v2e_k(const float* __restrict__ Y,
                                             float* __restrict__ out_edge) {
    int e = blockIdx.x * 4 + (threadIdx.x >> 5);
    if (e >= NE) return;
    int lane = threadIdx.x & 31;
    int sub = lane >> 4;
    int sl  = lane & 15;
    long beg = NODE_ARENA + (long)e * EDGE_CAP;
    int cnt = min((int)(__ldg(&g_cur[NN + e]) - beg), EDGE_CAP);

    float a[8] = {0.f, 0.f, 0.f, 0.f, 0.f, 0.f, 0.f, 0.f};
    gather16(reinterpret_cast<const uint4*>(g_xnorm), beg, cnt, sub, sl, lane, a);

    if (sub == 0) {
        int c0 = 8 * sl;
        long idx = (long)e * NC + c0;
        float4 sa = *reinterpret_cast<const float4*>(&g_s0[c0]);
        float4 sb = *reinterpret_cast<const float4*>(&g_s0[c0 + 4]);
        float4 ya = __ldg(reinterpret_cast<const float4*>(&Y[idx]));
        float4 yb = __ldg(reinterpret_cast<const float4*>(&Y[idx + 4]));
        float4 efa, efb;
        efa.x = sa.x * a[0] + (1.0f - sa.x) * ya.x;
        efa.y = sa.y * a[1] + (1.0f - sa.y) * ya.y;
        efa.z = sa.z * a[2] + (1.0f - sa.z) * ya.z;
        efa.w = sa.w * a[3] + (1.0f - sa.w) * ya.w;
        efb.x = sb.x * a[4] + (1.0f - sb.x) * yb.x;
        efb.y = sb.y * a[5] + (1.0f - sb.y) * yb.y;
        efb.z = sb.z * a[6] + (1.0f - sb.z) * yb.z;
        efb.w = sb.w * a[7] + (1.0f - sb.w) * yb.w;
        *reinterpret_cast<float4*>(&out_edge[idx])     = efa;
        *reinterpret_cast<float4*>(&out_edge[idx + 4]) = efb;
        float invde = (cnt > 0) ? (1.0f / (float)cnt) : 0.0f;
        uint4 p;
        __half2* ph = reinterpret_cast<__half2*>(&p);
        ph[0] = __floats2half2_rn(efa.x * invde, efa.y * invde);
        ph[1] = __floats2half2_rn(efa.z * invde, efa.w * invde);
        ph[2] = __floats2half2_rn(efb.x * invde, efb.y * invde);
        ph[3] = __floats2half2_rn(efb.z * invde, efb.w * invde);
        reinterpret_cast<uint4*>(g_enorm)[(long)e * NCU4 + sl] = p;
    }
}

// ---------------------------------------------------------------------------
// e2v: one WARP per node.
// ---------------------------------------------------------------------------
__global__ void __launch_bounds__(128) e2v_k(const float* __restrict__ X,
                                             float* __restrict__ out_node) {
    int n = blockIdx.x * 4 + (threadIdx.x >> 5);
    if (n >= NN) return;
    int lane = threadIdx.x & 31;
    int sub = lane >> 4;
    int sl  = lane & 15;
    long beg = (long)n * NODE_CAP;
    int cnt = min((int)(__ldg(&g_cur[n]) - beg), NODE_CAP);

    float a[8] = {0.f, 0.f, 0.f, 0.f, 0.f, 0.f, 0.f, 0.f};
    gather16(reinterpret_cast<const uint4*>(g_enorm), beg, cnt, sub, sl, lane, a);

    if (sub == 0) {
        int c0 = 8 * sl;
        long idx = (long)n * NC + c0;
        float4 sa = *reinterpret_cast<const float4*>(&g_s0[c0]);
        float4 sb = *reinterpret_cast<const float4*>(&g_s0[c0 + 4]);
        float4 xa = __ldg(reinterpret_cast<const float4*>(&X[idx]));
        float4 xb = __ldg(reinterpret_cast<const float4*>(&X[idx + 4]));
        float4 oa, ob;
        oa.x = sa.x * a[0] + (1.0f - sa.x) * xa.x;
        oa.y = sa.y * a[1] + (1.0f - sa.y) * xa.y;
        oa.z = sa.z * a[2] + (1.0f - sa.z) * xa.z;
        oa.w = sa.w * a[3] + (1.0f - sa.w) * xa.w;
        ob.x = sb.x * a[4] + (1.0f - sb.x) * xb.x;
        ob.y = sb.y * a[5] + (1.0f - sb.y) * xb.y;
        ob.z = sb.z * a[6] + (1.0f - sb.z) * xb.z;
        ob.w = sb.w * a[7] + (1.0f - sb.w) * xb.w;
        *reinterpret_cast<float4*>(&out_node[idx])     = oa;
        *reinterpret_cast<float4*>(&out_node[idx + 4]) = ob;
    }
}

// ---------------------------------------------------------------------------
extern "C" void kernel_launch(void* const* d_in, const int* in_sizes, int n_in,
                              void* d_out, int out_size) {
    const float* X  = (const float*)d_in[0];
    const float* Y  = (const float*)d_in[1];
    const float* lw = (const float*)d_in[2];
    const int*   ni = (const int*)d_in[3];
    const int*   ei = (const int*)d_in[4];

    float* out_node = (float*)d_out;
    float* out_edge = out_node + (long)NN * NC;

    init_cur<<<(NN + NE + 255) / 256, 256>>>(lw);
    fill_k<<<(NNZV + 255) / 256, 256>>>(ni, ei);
    {
        long tot = (long)NN * NC2;
        xnorm_k<<<(int)((tot + 255) / 256), 256>>>(X);
    }
    v2e_k<<<(NE + 3) / 4, 128>>>(Y, out_edge);
    e2v_k<<<(NN + 3) / 4, 128>>>(X, out_node);
}

// round 14
// speedup vs baseline: 1.4341x; 1.4341x over previous
#include <cuda_runtime.h>
#include <cuda_fp16.h>

// HyperDiffusion: N=100000, E=50000, C=128, NNZ=1600000.
// Bucket CSR + 32-lane warp-per-row fp16 gathers (uint2/lane — R13's 16-lane
// uint4 variant regressed via reg pressure + L1 wavefronts; reverted).
// This round: depth-2 HADD2 tree in the 32-lane layout + hoisted softmax.

#define NN        100000
#define NE        50000
#define NC        128
#define NC2       (NC / 2)        // 64 half2 per row
#define NCU2      (NC / 4)        // 32 uint2 (=4ch) per row
#define NNZV      1600000
#define NODE_CAP  96
#define EDGE_CAP  128
#define NODE_ARENA ((long)NN * NODE_CAP)              // 9.6M
#define ARENA_TOT  (NODE_ARENA + (long)NE * EDGE_CAP) // 16.0M ints

__device__ int    g_cur[NN + NE];                // fill cursors
__device__ int    g_payload[ARENA_TOT];          // PRE-SCALED uint2-row offsets (id*32)
__device__ float  g_s0[NC];                      // softmax(lazy_w)[0] per channel
__device__ __half g_xnorm[(size_t)NN * NC];      // X * inv_deg_v, fp16
__device__ __half g_enorm[(size_t)NE * NC];      // edge_feat * inv_deg_e, fp16

// ---------------------------------------------------------------------------
__global__ void init_cur(const float* __restrict__ lw) {
    int i = blockIdx.x * blockDim.x + threadIdx.x;
    if (i < NN) g_cur[i] = i * NODE_CAP;
    else if (i < NN + NE) g_cur[i] = (int)(NODE_ARENA + (long)(i - NN) * EDGE_CAP);
    if (i < NC) g_s0[i] = 1.0f / (1.0f + expf(lw[NC + i] - lw[i]));
}

// ---------------------------------------------------------------------------
__global__ void fill_k(const int* __restrict__ ni, const int* __restrict__ ei) {
    int i = blockIdx.x * blockDim.x + threadIdx.x;
    if (i >= NNZV) return;
    int n = ni[i];
    int e = ei[i];
    int p1 = atomicAdd(&g_cur[n], 1);
    int p2 = atomicAdd(&g_cur[NN + e], 1);
    if (p1 < n * NODE_CAP + NODE_CAP) g_payload[p1] = e * NCU2;
    if ((long)p2 < NODE_ARENA + (long)e * EDGE_CAP + EDGE_CAP) g_payload[p2] = n * NCU2;
}

// ---------------------------------------------------------------------------
__global__ void xnorm_k(const float* __restrict__ X) {
    long i = (long)blockIdx.x * blockDim.x + threadIdx.x;   // over NN*NC2
    if (i >= (long)NN * NC2) return;
    int n = (int)(i >> 6);                                  // NC2 = 64
    float2 x = reinterpret_cast<const float2*>(X)[i];
    int d = __ldg(&g_cur[n]) - n * NODE_CAP;
    float inv = (d > 0) ? (1.0f / (float)d) : 0.0f;
    reinterpret_cast<__half2*>(g_xnorm)[i] = __floats2half2_rn(x.x * inv, x.y * inv);
}

// ---------------------------------------------------------------------------
// fp16 helpers on uint2 (= 1 half2 pair)
// ---------------------------------------------------------------------------
__device__ __forceinline__ uint2 hadd2x2(uint2 x, uint2 y) {
    uint2 r;
    reinterpret_cast<__half2*>(&r)[0] =
        __hadd2(reinterpret_cast<const __half2*>(&x)[0],
                reinterpret_cast<const __half2*>(&y)[0]);
    reinterpret_cast<__half2*>(&r)[1] =
        __hadd2(reinterpret_cast<const __half2*>(&x)[1],
                reinterpret_cast<const __half2*>(&y)[1]);
    return r;
}

__device__ __forceinline__ void cvt_acc2(uint2 r, float& a0, float& a1,
                                         float& a2, float& a3) {
    float2 f0 = __half22float2(*reinterpret_cast<__half2*>(&r.x));
    float2 f1 = __half22float2(*reinterpret_cast<__half2*>(&r.y));
    a0 += f0.x; a1 += f0.y; a2 += f1.x; a3 += f1.y;
}

// ---------------------------------------------------------------------------
// 32-lane gather, depth-2 fp16 tree: 4 member rows combined in fp16 before
// one fp32 convert+accumulate. Lane owns 4 channels (1 uint2 per row).
// ---------------------------------------------------------------------------
__device__ __forceinline__ void gather_acc(const uint2* __restrict__ src,
                                           long beg, int cnt, int lane,
                                           float& a0, float& a1,
                                           float& a2, float& a3) {
    for (int base = 0; base < cnt; base += 32) {
        int k = base + lane;
        int m = (k < cnt) ? g_payload[beg + k] : 0;
        int lim = min(32, cnt - base);
        int j = 0;
        for (; j + 4 <= lim; j += 4) {
            int m0 = __shfl_sync(0xffffffffu, m, j);
            int m1 = __shfl_sync(0xffffffffu, m, j + 1);
            int m2 = __shfl_sync(0xffffffffu, m, j + 2);
            int m3 = __shfl_sync(0xffffffffu, m, j + 3);
            uint2 r0 = __ldg(&src[(unsigned)(m0 + lane)]);
            uint2 r1 = __ldg(&src[(unsigned)(m1 + lane)]);
            uint2 r2 = __ldg(&src[(unsigned)(m2 + lane)]);
            uint2 r3 = __ldg(&src[(unsigned)(m3 + lane)]);
            cvt_acc2(hadd2x2(hadd2x2(r0, r1), hadd2x2(r2, r3)), a0, a1, a2, a3);
        }
        for (; j < lim; j++) {
            int mi = __shfl_sync(0xffffffffu, m, j);
            cvt_acc2(__ldg(&src[(unsigned)(mi + lane)]), a0, a1, a2, a3);
        }
    }
}

// ---------------------------------------------------------------------------
// v2e: one WARP per edge. Lane owns channels [4*lane, 4*lane+4).
// ---------------------------------------------------------------------------
__global__ void __launch_bounds__(128) v2e_k(const float* __restrict__ Y,
                                             float* __restrict__ out_edge) {
    int e = blockIdx.x * 4 + (threadIdx.x >> 5);
    if (e >= NE) return;
    int lane = threadIdx.x & 31;
    long beg = NODE_ARENA + (long)e * EDGE_CAP;
    int cnt = min((int)(__ldg(&g_cur[NN + e]) - beg), EDGE_CAP);

    float a0 = 0.f, a1 = 0.f, a2 = 0.f, a3 = 0.f;
    gather_acc(reinterpret_cast<const uint2*>(g_xnorm), beg, cnt, lane, a0, a1, a2, a3);

    int c0 = 4 * lane;
    float4 s = *reinterpret_cast<const float4*>(&g_s0[c0]);
    long idx = (long)e * NC + c0;
    float4 y = __ldg(reinterpret_cast<const float4*>(&Y[idx]));
    float4 ef;
    ef.x = s.x * a0 + (1.0f - s.x) * y.x;
    ef.y = s.y * a1 + (1.0f - s.y) * y.y;
    ef.z = s.z * a2 + (1.0f - s.z) * y.z;
    ef.w = s.w * a3 + (1.0f - s.w) * y.w;
    *reinterpret_cast<float4*>(&out_edge[idx]) = ef;
    float invde = (cnt > 0) ? (1.0f / (float)cnt) : 0.0f;
    uint2 packed;
    *reinterpret_cast<__half2*>(&packed.x) = __floats2half2_rn(ef.x * invde, ef.y * invde);
    *reinterpret_cast<__half2*>(&packed.y) = __floats2half2_rn(ef.z * invde, ef.w * invde);
    reinterpret_cast<uint2*>(g_enorm)[(long)e * NCU2 + lane] = packed;
}

// ---------------------------------------------------------------------------
// e2v: one WARP per node, same structure.
// ---------------------------------------------------------------------------
__global__ void __launch_bounds__(128) e2v_k(const float* __restrict__ X,
                                             float* __restrict__ out_node) {
    int n = blockIdx.x * 4 + (threadIdx.x >> 5);
    if (n >= NN) return;
    int lane = threadIdx.x & 31;
    long beg = (long)n * NODE_CAP;
    int cnt = min((int)(__ldg(&g_cur[n]) - beg), NODE_CAP);

    float a0 = 0.f, a1 = 0.f, a2 = 0.f, a3 = 0.f;
    gather_acc(reinterpret_cast<const uint2*>(g_enorm), beg, cnt, lane, a0, a1, a2, a3);

    int c0 = 4 * lane;
    float4 s = *reinterpret_cast<const float4*>(&g_s0[c0]);
    long idx = (long)n * NC + c0;
    float4 x = __ldg(reinterpret_cast<const float4*>(&X[idx]));
    float4 o;
    o.x = s.x * a0 + (1.0f - s.x) * x.x;
    o.y = s.y * a1 + (1.0f - s.y) * x.y;
    o.z = s.z * a2 + (1.0f - s.z) * x.z;
    o.w = s.w * a3 + (1.0f - s.w) * x.w;
    *reinterpret_cast<float4*>(&out_node[idx]) = o;
}

// ---------------------------------------------------------------------------
extern "C" void kernel_launch(void* const* d_in, const int* in_sizes, int n_in,
                              void* d_out, int out_size) {
    const float* X  = (const float*)d_in[0];
    const float* Y  = (const float*)d_in[1];
    const float* lw = (const float*)d_in[2];
    const int*   ni = (const int*)d_in[3];
    const int*   ei = (const int*)d_in[4];

    float* out_node = (float*)d_out;
    float* out_edge = out_node + (long)NN * NC;

    init_cur<<<(NN + NE + 255) / 256, 256>>>(lw);
    fill_k<<<(NNZV + 255) / 256, 256>>>(ni, ei);
    {
        long tot = (long)NN * NC2;
        xnorm_k<<<(int)((tot + 255) / 256), 256>>>(X);
    }
    v2e_k<<<(NE + 3) / 4, 128>>>(Y, out_edge);
    e2v_k<<<(NN + 3) / 4, 128>>>(X, out_node);
}

// round 17
// speedup vs baseline: 1.4529x; 1.0131x over previous
#include <cuda_runtime.h>
#include <cuda_fp16.h>

// HyperDiffusion: N=100000, E=50000, C=128, NNZ=1600000.
// Bucket CSR + 32-lane warp-per-row fp16 gathers, depth-2 HADD2 tree.
// This round: zero-row padding to multiple-of-4 bucket lengths → gather
// inner loop has no tail, no predicates, no guarded payload load.

#define NN        100000
#define NE        50000
#define NC        128
#define NC2       (NC / 2)        // 64 half2 per row
#define NCU2      (NC / 4)        // 32 uint2 (=4ch) per row
#define NNZV      1600000
#define MROWS     (NN + NE)
#define NODE_CAP  96
#define EDGE_CAP  128
#define NODE_ARENA (NN * NODE_CAP)                    // 9.6M (int-safe)
#define ARENA_TOT  (NODE_ARENA + NE * EDGE_CAP)       // 16.0M ints
#define ZERO_X     (NN * NCU2)    // zero row index in g_xnorm (uint2 units)
#define ZERO_E     (NE * NCU2)    // zero row index in g_enorm (uint2 units)

__device__ int    g_cur[MROWS];                   // fill cursors
__device__ int    g_payload[ARENA_TOT];           // PRE-SCALED uint2-row offsets
__device__ float  g_s0[NC];                       // softmax(lazy_w)[0] per channel
__device__ __half g_xnorm[(size_t)(NN + 1) * NC]; // + zero row (never written)
__device__ __half g_enorm[(size_t)(NE + 1) * NC]; // + zero row (never written)

// ---------------------------------------------------------------------------
__global__ void init_cur(const float* __restrict__ lw) {
    int i = blockIdx.x * blockDim.x + threadIdx.x;
    if (i < NN) g_cur[i] = i * NODE_CAP;
    else if (i < MROWS) g_cur[i] = NODE_ARENA + (i - NN) * EDGE_CAP;
    if (i < NC) g_s0[i] = 1.0f / (1.0f + expf(lw[NC + i] - lw[i]));
}

// ---------------------------------------------------------------------------
__global__ void fill_k(const int* __restrict__ ni, const int* __restrict__ ei) {
    int i = blockIdx.x * blockDim.x + threadIdx.x;
    if (i >= NNZV) return;
    int n = ni[i];
    int e = ei[i];
    int p1 = atomicAdd(&g_cur[n], 1);
    int p2 = atomicAdd(&g_cur[NN + e], 1);
    if (p1 < n * NODE_CAP + NODE_CAP) g_payload[p1] = e * NCU2;
    if (p2 < NODE_ARENA + e * EDGE_CAP + EDGE_CAP) g_payload[p2] = n * NCU2;
}

// ---------------------------------------------------------------------------
// xnorm + bucket padding (independent jobs, fused to save a launch).
// Threads < MROWS pad their bucket to a multiple of 4 with zero-row ptrs;
// all threads grid-stride the fp16 xnorm conversion.
// ---------------------------------------------------------------------------
__global__ void xnorm_pad_k(const float* __restrict__ X) {
    long i = (long)blockIdx.x * blockDim.x + threadIdx.x;
    if (i < MROWS) {
        int r = (int)i;
        int base, cap, padval;
        if (r < NN) { base = r * NODE_CAP; cap = NODE_CAP; padval = ZERO_E; }
        else { base = NODE_ARENA + (r - NN) * EDGE_CAP; cap = EDGE_CAP; padval = ZERO_X; }
        int end = g_cur[r];
        int deg = min(end - base, cap);
        int tgt = base + ((deg + 3) & ~3);
        for (int p = end; p < tgt; p++) g_payload[p] = padval;
    }
    if (i < (long)NN * NC2) {
        int n = (int)(i >> 6);                                  // NC2 = 64
        float2 x = reinterpret_cast<const float2*>(X)[i];
        int d = __ldg(&g_cur[n]) - n * NODE_CAP;
        float inv = (d > 0) ? (1.0f / (float)d) : 0.0f;
        reinterpret_cast<__half2*>(g_xnorm)[i] = __floats2half2_rn(x.x * inv, x.y * inv);
    }
}

// ---------------------------------------------------------------------------
// fp16 helpers on uint2 (= 2 half2)
// ---------------------------------------------------------------------------
__device__ __forceinline__ uint2 hadd2x2(uint2 x, uint2 y) {
    uint2 r;
    reinterpret_cast<__half2*>(&r)[0] =
        __hadd2(reinterpret_cast<const __half2*>(&x)[0],
                reinterpret_cast<const __half2*>(&y)[0]);
    reinterpret_cast<__half2*>(&r)[1] =
        __hadd2(reinterpret_cast<const __half2*>(&x)[1],
                reinterpret_cast<const __half2*>(&y)[1]);
    return r;
}

__device__ __forceinline__ void cvt_acc2(uint2 r, float& a0, float& a1,
                                         float& a2, float& a3) {
    float2 f0 = __half22float2(*reinterpret_cast<__half2*>(&r.x));
    float2 f1 = __half22float2(*reinterpret_cast<__half2*>(&r.y));
    a0 += f0.x; a1 += f0.y; a2 += f1.x; a3 += f1.y;
}

// ---------------------------------------------------------------------------
// Tail-free gather: cnt_pad is a multiple of 4; payload [beg, beg+cnt_pad)
// is fully valid (pad entries point at the zero row). No predicates.
// ---------------------------------------------------------------------------
__device__ __forceinline__ void gather_acc(const uint2* __restrict__ src,
                                           int beg, int cnt_pad, int lane,
                                           float& a0, float& a1,
                                           float& a2, float& a3) {
    for (int base = 0; base < cnt_pad; base += 32) {
        int m = g_payload[beg + base + lane];    // unguarded: arena-valid
        int steps = min(32, cnt_pad - base);     // multiple of 4
        for (int j = 0; j < steps; j += 4) {
            int m0 = __shfl_sync(0xffffffffu, m, j);
            int m1 = __shfl_sync(0xffffffffu, m, j + 1);
            int m2 = __shfl_sync(0xffffffffu, m, j + 2);
            int m3 = __shfl_sync(0xffffffffu, m, j + 3);
            uint2 r0 = __ldg(&src[(unsigned)(m0 + lane)]);
            uint2 r1 = __ldg(&src[(unsigned)(m1 + lane)]);
            uint2 r2 = __ldg(&src[(unsigned)(m2 + lane)]);
            uint2 r3 = __ldg(&src[(unsigned)(m3 + lane)]);
            cvt_acc2(hadd2x2(hadd2x2(r0, r1), hadd2x2(r2, r3)), a0, a1, a2, a3);
        }
    }
}

// ---------------------------------------------------------------------------
// v2e: one WARP per edge. Lane owns channels [4*lane, 4*lane+4).
// ---------------------------------------------------------------------------
__global__ void __launch_bounds__(128) v2e_k(const float* __restrict__ Y,
                                             float* __restrict__ out_edge) {
    int e = blockIdx.x * 4 + (threadIdx.x >> 5);
    if (e >= NE) return;
    int lane = threadIdx.x & 31;
    int beg = NODE_ARENA + e * EDGE_CAP;
    int cnt = min(__ldg(&g_cur[NN + e]) - beg, EDGE_CAP);
    int cnt_pad = (cnt + 3) & ~3;

    float a0 = 0.f, a1 = 0.f, a2 = 0.f, a3 = 0.f;
    gather_acc(reinterpret_cast<const uint2*>(g_xnorm), beg, cnt_pad, lane,
               a0, a1, a2, a3);

    int c0 = 4 * lane;
    float4 s = *reinterpret_cast<const float4*>(&g_s0[c0]);
    long idx = (long)e * NC + c0;
    float4 y = __ldg(reinterpret_cast<const float4*>(&Y[idx]));
    float4 ef;
    ef.x = s.x * a0 + (1.0f - s.x) * y.x;
    ef.y = s.y * a1 + (1.0f - s.y) * y.y;
    ef.z = s.z * a2 + (1.0f - s.z) * y.z;
    ef.w = s.w * a3 + (1.0f - s.w) * y.w;
    *reinterpret_cast<float4*>(&out_edge[idx]) = ef;
    float invde = (cnt > 0) ? (1.0f / (float)cnt) : 0.0f;
    uint2 packed;
    *reinterpret_cast<__half2*>(&packed.x) = __floats2half2_rn(ef.x * invde, ef.y * invde);
    *reinterpret_cast<__half2*>(&packed.y) = __floats2half2_rn(ef.z * invde, ef.w * invde);
    reinterpret_cast<uint2*>(g_enorm)[(long)e * NCU2 + lane] = packed;
}

// ---------------------------------------------------------------------------
// e2v: one WARP per node, same structure.
// ---------------------------------------------------------------------------
__global__ void __launch_bounds__(128) e2v_k(const float* __restrict__ X,
                                             float* __restrict__ out_node) {
    int n = blockIdx.x * 4 + (threadIdx.x >> 5);
    if (n >= NN) return;
    int lane = threadIdx.x & 31;
    int beg = n * NODE_CAP;
    int cnt = min(__ldg(&g_cur[n]) - beg, NODE_CAP);
    int cnt_pad = (cnt + 3) & ~3;

    float a0 = 0.f, a1 = 0.f, a2 = 0.f, a3 = 0.f;
    gather_acc(reinterpret_cast<const uint2*>(g_enorm), beg, cnt_pad, lane,
               a0, a1, a2, a3);

    int c0 = 4 * lane;
    float4 s = *reinterpret_cast<const float4*>(&g_s0[c0]);
    long idx = (long)n * NC + c0;
    float4 x = __ldg(reinterpret_cast<const float4*>(&X[idx]));
    float4 o;
    o.x = s.x * a0 + (1.0f - s.x) * x.x;
    o.y = s.y * a1 + (1.0f - s.y) * x.y;
    o.z = s.z * a2 + (1.0f - s.z) * x.z;
    o.w = s.w * a3 + (1.0f - s.w) * x.w;
    *reinterpret_cast<float4*>(&out_node[idx]) = o;
}

// ---------------------------------------------------------------------------
extern "C" void kernel_launch(void* const* d_in, const int* in_sizes, int n_in,
                              void* d_out, int out_size) {
    const float* X  = (const float*)d_in[0];
    const float* Y  = (const float*)d_in[1];
    const float* lw = (const float*)d_in[2];
    const int*   ni = (const int*)d_in[3];
    const int*   ei = (const int*)d_in[4];

    float* out_node = (float*)d_out;
    float* out_edge = out_node + (long)NN * NC;

    init_cur<<<(MROWS + 255) / 256, 256>>>(lw);
    fill_k<<<(NNZV + 255) / 256, 256>>>(ni, ei);
    {
        long tot = (long)NN * NC2;
        xnorm_pad_k<<<(int)((tot + 255) / 256), 256>>>(X);
    }
    v2e_k<<<(NE + 3) / 4, 128>>>(Y, out_edge);
    e2v_k<<<(NN + 3) / 4, 128>>>(X, out_node);
}